// round 1
// baseline (speedup 1.0000x reference)
#include <cuda_runtime.h>

#define HD 128
#define HHD 64
#define NMAX 100000

// ---------------- device scratch (no allocations allowed) ----------------
__device__ float g_inv_feat[NMAX * HD];   // mlp_inv(feat) for every node
__device__ float g_nsum[NMAX * HD];       // segment sum of messages
__device__ float g_deg[NMAX];             // in-degree (float)

// ---------------- shared memory layout for MLP kernels ----------------
struct SmemT {
  float xs[128 * 128];   // input tile / res tile (stride 128)
  float ws[128 * 64];    // one weight layer, swizzled (max 8192 floats)
  float as1[128 * 64];   // activation buffer (stride 64)
  float as2[128 * 64];   // activation buffer (stride 64)
  float bias[128];
};

extern __shared__ float smem_dyn[];

// Stage one weight layer [C][K] row-major from gmem into smem with an XOR
// swizzle on the 16B slot index so the GEMM b-loads are <=2-way conflicted.
__device__ __forceinline__ void load_weights(const float* __restrict__ wg,
                                             const float* __restrict__ bg,
                                             int C, int K, float* ws,
                                             float* bias) {
  const int slots = K >> 2;          // float4 slots per row
  const int total = C * slots;
  const float4* wg4 = (const float4*)wg;
  float4* ws4 = (float4*)ws;
  for (int i = threadIdx.x; i < total; i += 256) {
    int c = i / slots;
    int s = i - c * slots;
    int swz = (c >> 2) & 7;
    ws4[c * slots + (s ^ swz)] = wg4[i];
  }
  if ((int)threadIdx.x < C) bias[threadIdx.x] = bg[threadIdx.x];
}

// One GEMM stage: out[r][c] = act( in[r][:] . w[c][:] + bias[c] )
// R = 128 rows, 256 threads, thread tile = 8 rows x 4 cols (x C/64 passes).
// OUTMODE: 0 = write smem out_s (stride C)
//          1 = write global out_g rows (stride HD), guarded by N
//          2 = write global with per-row select: inv ? acc : res_s
template <int K, int C, bool RELU, int OUTMODE>
__device__ __forceinline__ void gemm_stage(
    const float* __restrict__ in_s, const float* __restrict__ ws,
    const float* __restrict__ bias, float* __restrict__ out_s,
    float* __restrict__ out_g, const float* __restrict__ res_s,
    const int* __restrict__ invflag, int row0, int N) {
  const int tid = threadIdx.x;
  const int rg = tid >> 4;      // 0..15 -> rows rg*8 .. rg*8+7
  const int cg0 = tid & 15;     // 0..15 -> cols cg*4 .. cg*4+3
  constexpr int SL = K >> 2;    // float4 slots per row
  const float4* in4 = (const float4*)in_s;
  const float4* w4 = (const float4*)ws;

#pragma unroll
  for (int cc = 0; cc < C / 64; ++cc) {
    const int cg = cg0 + (cc << 4);
    const int c0 = cg << 2;
    const int swz = cg & 7;
    float acc[8][4];
#pragma unroll
    for (int i = 0; i < 8; ++i)
#pragma unroll
      for (int j = 0; j < 4; ++j) acc[i][j] = 0.f;

    const float4* wrow0 = w4 + (c0 + 0) * SL;
    const float4* wrow1 = w4 + (c0 + 1) * SL;
    const float4* wrow2 = w4 + (c0 + 2) * SL;
    const float4* wrow3 = w4 + (c0 + 3) * SL;
    const float4* arow = in4 + (rg * 8) * SL;

#pragma unroll 4
    for (int s = 0; s < SL; ++s) {
      const int ss = s ^ swz;
      float4 b0 = wrow0[ss];
      float4 b1 = wrow1[ss];
      float4 b2 = wrow2[ss];
      float4 b3 = wrow3[ss];
#pragma unroll
      for (int i = 0; i < 8; ++i) {
        float4 a = arow[i * SL + s];
        acc[i][0] = fmaf(a.x, b0.x, acc[i][0]);
        acc[i][0] = fmaf(a.y, b0.y, acc[i][0]);
        acc[i][0] = fmaf(a.z, b0.z, acc[i][0]);
        acc[i][0] = fmaf(a.w, b0.w, acc[i][0]);
        acc[i][1] = fmaf(a.x, b1.x, acc[i][1]);
        acc[i][1] = fmaf(a.y, b1.y, acc[i][1]);
        acc[i][1] = fmaf(a.z, b1.z, acc[i][1]);
        acc[i][1] = fmaf(a.w, b1.w, acc[i][1]);
        acc[i][2] = fmaf(a.x, b2.x, acc[i][2]);
        acc[i][2] = fmaf(a.y, b2.y, acc[i][2]);
        acc[i][2] = fmaf(a.z, b2.z, acc[i][2]);
        acc[i][2] = fmaf(a.w, b2.w, acc[i][2]);
        acc[i][3] = fmaf(a.x, b3.x, acc[i][3]);
        acc[i][3] = fmaf(a.y, b3.y, acc[i][3]);
        acc[i][3] = fmaf(a.z, b3.z, acc[i][3]);
        acc[i][3] = fmaf(a.w, b3.w, acc[i][3]);
      }
    }

    const float bx = bias[c0 + 0];
    const float by = bias[c0 + 1];
    const float bz = bias[c0 + 2];
    const float bw = bias[c0 + 3];
#pragma unroll
    for (int i = 0; i < 8; ++i) {
      const int r = rg * 8 + i;
      float4 o;
      o.x = acc[i][0] + bx;
      o.y = acc[i][1] + by;
      o.z = acc[i][2] + bz;
      o.w = acc[i][3] + bw;
      if (RELU) {
        o.x = o.x >= 0.f ? o.x : 0.01f * o.x;
        o.y = o.y >= 0.f ? o.y : 0.01f * o.y;
        o.z = o.z >= 0.f ? o.z : 0.01f * o.z;
        o.w = o.w >= 0.f ? o.w : 0.01f * o.w;
      }
      if (OUTMODE == 0) {
        ((float4*)out_s)[(r * C + c0) >> 2] = o;
      } else {
        const int row = row0 + r;
        if (row < N) {
          if (OUTMODE == 2) {
            if (__ldg(invflag + row) == 0)
              o = ((const float4*)res_s)[(r * HD + c0) >> 2];
          }
          ((float4*)out_g)[(((size_t)row) * HD + c0) >> 2] = o;
        }
      }
    }
  }
}

// ---------------- kernel A: inv_feat = mlp3_inv(feat) ----------------
__global__ __launch_bounds__(256, 1) void mlp_inv_kernel(
    const float* __restrict__ feat, const float* __restrict__ w1,
    const float* __restrict__ b1, const float* __restrict__ w2,
    const float* __restrict__ b2, const float* __restrict__ w3,
    const float* __restrict__ b3, float* __restrict__ outg, int N) {
  SmemT* S = (SmemT*)smem_dyn;
  const int row0 = blockIdx.x * 128;
  const float4* f4 = (const float4*)feat;
  for (int i = threadIdx.x; i < 128 * 32; i += 256) {
    int r = i >> 5, kq = i & 31;
    int row = row0 + r;
    float4 v = make_float4(0.f, 0.f, 0.f, 0.f);
    if (row < N) v = __ldg(&f4[(size_t)row * 32 + kq]);
    ((float4*)S->xs)[r * 32 + kq] = v;
  }
  load_weights(w1, b1, HHD, HD, S->ws, S->bias);
  __syncthreads();
  gemm_stage<HD, HHD, true, 0>(S->xs, S->ws, S->bias, S->as1, nullptr, nullptr,
                               nullptr, row0, N);
  __syncthreads();
  load_weights(w2, b2, HHD, HHD, S->ws, S->bias);
  __syncthreads();
  gemm_stage<HHD, HHD, true, 0>(S->as1, S->ws, S->bias, S->as2, nullptr,
                                nullptr, nullptr, row0, N);
  __syncthreads();
  load_weights(w3, b3, HD, HHD, S->ws, S->bias);
  __syncthreads();
  gemm_stage<HHD, HD, false, 1>(S->as2, S->ws, S->bias, nullptr, outg, nullptr,
                                nullptr, row0, N);
}

// ---------------- kernel B: edge gather + scatter-add ----------------
__global__ __launch_bounds__(256) void scatter_kernel(
    const float* __restrict__ feat, const float* __restrict__ invf,
    const int* __restrict__ src, const int* __restrict__ dst,
    const int* __restrict__ r, float* __restrict__ nsum,
    float* __restrict__ deg, int E) {
  const int e = blockIdx.x * 8 + (threadIdx.x >> 5);
  if (e >= E) return;
  const int lane = threadIdx.x & 31;
  const int s = __ldg(src + e);
  const int d = __ldg(dst + e);
  const int rr = __ldg(r + e);
  const float* base = rr ? invf : feat;
  const float4 v = __ldg((const float4*)(base + (size_t)s * HD) + lane);
  float* o = nsum + (size_t)d * HD + lane * 4;
  atomicAdd(o + 0, v.x);
  atomicAdd(o + 1, v.y);
  atomicAdd(o + 2, v.z);
  atomicAdd(o + 3, v.w);
  if (lane == 0) atomicAdd(deg + d, 1.0f);
}

// --------- kernel C: node apply: mean -> and-MLP -> inv-MLP -> select ---------
__global__ __launch_bounds__(256, 1) void node_kernel(
    const float* __restrict__ nsum, const float* __restrict__ deg,
    const float* __restrict__ aw1, const float* __restrict__ ab1,
    const float* __restrict__ aw2, const float* __restrict__ ab2,
    const float* __restrict__ aw3, const float* __restrict__ ab3,
    const float* __restrict__ iw1, const float* __restrict__ ib1,
    const float* __restrict__ iw2, const float* __restrict__ ib2,
    const float* __restrict__ iw3, const float* __restrict__ ib3,
    const int* __restrict__ inv, float* __restrict__ outg, int N) {
  SmemT* S = (SmemT*)smem_dyn;
  const int row0 = blockIdx.x * 128;
  const float4* n4 = (const float4*)nsum;
  for (int i = threadIdx.x; i < 128 * 32; i += 256) {
    int r = i >> 5, kq = i & 31;
    int row = row0 + r;
    float4 v = make_float4(0.f, 0.f, 0.f, 0.f);
    if (row < N) {
      float invd = 1.0f / fmaxf(__ldg(deg + row), 1.0f);
      v = __ldg(&n4[(size_t)row * 32 + kq]);
      v.x *= invd; v.y *= invd; v.z *= invd; v.w *= invd;
    }
    ((float4*)S->xs)[r * 32 + kq] = v;
  }
  // and-MLP
  load_weights(aw1, ab1, HHD, HD, S->ws, S->bias);
  __syncthreads();
  gemm_stage<HD, HHD, true, 0>(S->xs, S->ws, S->bias, S->as1, nullptr, nullptr,
                               nullptr, row0, N);
  __syncthreads();
  load_weights(aw2, ab2, HHD, HHD, S->ws, S->bias);
  __syncthreads();
  gemm_stage<HHD, HHD, true, 0>(S->as1, S->ws, S->bias, S->as2, nullptr,
                                nullptr, nullptr, row0, N);
  __syncthreads();
  load_weights(aw3, ab3, HD, HHD, S->ws, S->bias);
  __syncthreads();
  // res -> xs (stride 128), no activation
  gemm_stage<HHD, HD, false, 0>(S->as2, S->ws, S->bias, S->xs, nullptr,
                                nullptr, nullptr, row0, N);
  __syncthreads();
  // inv-MLP on res
  load_weights(iw1, ib1, HHD, HD, S->ws, S->bias);
  __syncthreads();
  gemm_stage<HD, HHD, true, 0>(S->xs, S->ws, S->bias, S->as1, nullptr, nullptr,
                               nullptr, row0, N);
  __syncthreads();
  load_weights(iw2, ib2, HHD, HHD, S->ws, S->bias);
  __syncthreads();
  gemm_stage<HHD, HHD, true, 0>(S->as1, S->ws, S->bias, S->as2, nullptr,
                                nullptr, nullptr, row0, N);
  __syncthreads();
  load_weights(iw3, ib3, HD, HHD, S->ws, S->bias);
  __syncthreads();
  // final: out = inv ? mlp_inv(res) : res
  gemm_stage<HHD, HD, false, 2>(S->as2, S->ws, S->bias, nullptr, outg, S->xs,
                                inv, row0, N);
}

// ---------------- launch ----------------
extern "C" void kernel_launch(void* const* d_in, const int* in_sizes, int n_in,
                              void* d_out, int out_size) {
  const float* feat = (const float*)d_in[0];
  const int* src = (const int*)d_in[1];
  const int* dst = (const int*)d_in[2];
  const int* r = (const int*)d_in[3];
  const int* inv = (const int*)d_in[4];
  const float* iw1 = (const float*)d_in[5];
  const float* ib1 = (const float*)d_in[6];
  const float* iw2 = (const float*)d_in[7];
  const float* ib2 = (const float*)d_in[8];
  const float* iw3 = (const float*)d_in[9];
  const float* ib3 = (const float*)d_in[10];
  const float* aw1 = (const float*)d_in[11];
  const float* ab1 = (const float*)d_in[12];
  const float* aw2 = (const float*)d_in[13];
  const float* ab2 = (const float*)d_in[14];
  const float* aw3 = (const float*)d_in[15];
  const float* ab3 = (const float*)d_in[16];
  float* out = (float*)d_out;

  const int N = in_sizes[0] / HD;
  const int E = in_sizes[1];

  float *p_invf, *p_nsum, *p_deg;
  cudaGetSymbolAddress((void**)&p_invf, g_inv_feat);
  cudaGetSymbolAddress((void**)&p_nsum, g_nsum);
  cudaGetSymbolAddress((void**)&p_deg, g_deg);

  const int smem = (int)sizeof(SmemT);
  cudaFuncSetAttribute(mlp_inv_kernel,
                       cudaFuncAttributeMaxDynamicSharedMemorySize, smem);
  cudaFuncSetAttribute(node_kernel,
                       cudaFuncAttributeMaxDynamicSharedMemorySize, smem);

  cudaMemsetAsync(p_nsum, 0, (size_t)N * HD * sizeof(float));
  cudaMemsetAsync(p_deg, 0, (size_t)N * sizeof(float));

  const int nblocks = (N + 127) / 128;
  mlp_inv_kernel<<<nblocks, 256, smem>>>(feat, iw1, ib1, iw2, ib2, iw3, ib3,
                                         p_invf, N);
  scatter_kernel<<<(E + 7) / 8, 256>>>(feat, p_invf, src, dst, r, p_nsum,
                                       p_deg, E);
  node_kernel<<<nblocks, 256, smem>>>(p_nsum, p_deg, aw1, ab1, aw2, ab2, aw3,
                                      ab3, iw1, ib1, iw2, ib2, iw3, ib3, inv,
                                      out, N);
}

// round 4
// speedup vs baseline: 1.0763x; 1.0763x over previous
#include <cuda_runtime.h>

#define HD 128
#define HHD 64
#define NMAX 100000

// ---------------- device scratch (no allocations allowed) ----------------
__device__ float g_inv_feat[NMAX * HD];   // mlp_inv(feat) for every node
__device__ float g_nsum[NMAX * HD];       // segment sum of messages
__device__ float g_deg[NMAX];             // in-degree (float)

// ---------------- shared memory layout for MLP kernels ----------------
struct SmemT {
  float xs[128 * 128];   // input tile / res tile (stride 128)
  float ws[128 * 64];    // one weight layer, swizzled (max 8192 floats)
  float as1[128 * 64];   // activation buffer (stride 64)
  float as2[128 * 64];   // activation buffer (stride 64)
  float bias[128];
};

extern __shared__ float smem_dyn[];

// Stage one weight layer [C][K] row-major from gmem into smem with an XOR
// swizzle on the 16B slot index so the GEMM b-loads are <=2-way conflicted.
__device__ __forceinline__ void load_weights(const float* __restrict__ wg,
                                             const float* __restrict__ bg,
                                             int C, int K, float* ws,
                                             float* bias) {
  const int slots = K >> 2;          // float4 slots per row
  const int total = C * slots;
  const float4* wg4 = (const float4*)wg;
  float4* ws4 = (float4*)ws;
  for (int i = threadIdx.x; i < total; i += 512) {
    int c = i / slots;
    int s = i - c * slots;
    int swz = (c >> 2) & 7;
    ws4[c * slots + (s ^ swz)] = __ldg(&wg4[i]);
  }
  if ((int)threadIdx.x < C) bias[threadIdx.x] = __ldg(bg + threadIdx.x);
}

// One GEMM stage: out[r][c] = act( in[r][:] . w[c][:] + bias[c] )
// 128 rows, 512 threads, thread tile = 4 rows x 4 cols (x C/64 passes).
// OUTMODE: 0 = write smem out_s (stride C)
//          1 = write global out_g rows (stride HD), guarded by N
//          2 = write global with per-row select: inv ? acc : res_s
template <int K, int C, bool RELU, int OUTMODE>
__device__ __forceinline__ void gemm_stage(
    const float* __restrict__ in_s, const float* __restrict__ ws,
    const float* __restrict__ bias, float* __restrict__ out_s,
    float* __restrict__ out_g, const float* __restrict__ res_s,
    const int* __restrict__ invflag, int row0, int N) {
  const int tid = threadIdx.x;
  const int rg = tid >> 4;      // 0..31 -> rows rg*4 .. rg*4+3
  const int cg0 = tid & 15;     // 0..15 -> cols cg*4 .. cg*4+3
  constexpr int SL = K >> 2;    // float4 slots per row
  const float4* in4 = (const float4*)in_s;
  const float4* w4 = (const float4*)ws;

#pragma unroll
  for (int cc = 0; cc < C / 64; ++cc) {
    const int cg = cg0 + (cc << 4);
    const int c0 = cg << 2;
    const int swz = cg & 7;
    float acc[4][4];
#pragma unroll
    for (int i = 0; i < 4; ++i)
#pragma unroll
      for (int j = 0; j < 4; ++j) acc[i][j] = 0.f;

    const float4* wrow0 = w4 + (c0 + 0) * SL;
    const float4* wrow1 = w4 + (c0 + 1) * SL;
    const float4* wrow2 = w4 + (c0 + 2) * SL;
    const float4* wrow3 = w4 + (c0 + 3) * SL;
    const float4* arow = in4 + (rg * 4) * SL;

#pragma unroll 4
    for (int s = 0; s < SL; ++s) {
      const int ss = s ^ swz;
      float4 b0 = wrow0[ss];
      float4 b1 = wrow1[ss];
      float4 b2 = wrow2[ss];
      float4 b3 = wrow3[ss];
#pragma unroll
      for (int i = 0; i < 4; ++i) {
        float4 a = arow[i * SL + s];
        acc[i][0] = fmaf(a.x, b0.x, acc[i][0]);
        acc[i][0] = fmaf(a.y, b0.y, acc[i][0]);
        acc[i][0] = fmaf(a.z, b0.z, acc[i][0]);
        acc[i][0] = fmaf(a.w, b0.w, acc[i][0]);
        acc[i][1] = fmaf(a.x, b1.x, acc[i][1]);
        acc[i][1] = fmaf(a.y, b1.y, acc[i][1]);
        acc[i][1] = fmaf(a.z, b1.z, acc[i][1]);
        acc[i][1] = fmaf(a.w, b1.w, acc[i][1]);
        acc[i][2] = fmaf(a.x, b2.x, acc[i][2]);
        acc[i][2] = fmaf(a.y, b2.y, acc[i][2]);
        acc[i][2] = fmaf(a.z, b2.z, acc[i][2]);
        acc[i][2] = fmaf(a.w, b2.w, acc[i][2]);
        acc[i][3] = fmaf(a.x, b3.x, acc[i][3]);
        acc[i][3] = fmaf(a.y, b3.y, acc[i][3]);
        acc[i][3] = fmaf(a.z, b3.z, acc[i][3]);
        acc[i][3] = fmaf(a.w, b3.w, acc[i][3]);
      }
    }

    const float bx = bias[c0 + 0];
    const float by = bias[c0 + 1];
    const float bz = bias[c0 + 2];
    const float bw = bias[c0 + 3];
#pragma unroll
    for (int i = 0; i < 4; ++i) {
      const int r = rg * 4 + i;
      float4 o;
      o.x = acc[i][0] + bx;
      o.y = acc[i][1] + by;
      o.z = acc[i][2] + bz;
      o.w = acc[i][3] + bw;
      if (RELU) {
        o.x = o.x >= 0.f ? o.x : 0.01f * o.x;
        o.y = o.y >= 0.f ? o.y : 0.01f * o.y;
        o.z = o.z >= 0.f ? o.z : 0.01f * o.z;
        o.w = o.w >= 0.f ? o.w : 0.01f * o.w;
      }
      if (OUTMODE == 0) {
        ((float4*)out_s)[(r * C + c0) >> 2] = o;
      } else {
        const int row = row0 + r;
        if (row < N) {
          if (OUTMODE == 2) {
            if (__ldg(invflag + row) == 0)
              o = ((const float4*)res_s)[(r * HD + c0) >> 2];
          }
          ((float4*)out_g)[(((size_t)row) * HD + c0) >> 2] = o;
        }
      }
    }
  }
}

// ---------------- kernel A: inv_feat = mlp3_inv(feat) ----------------
__global__ __launch_bounds__(512, 1) void mlp_inv_kernel(
    const float* __restrict__ feat, const float* __restrict__ w1,
    const float* __restrict__ b1, const float* __restrict__ w2,
    const float* __restrict__ b2, const float* __restrict__ w3,
    const float* __restrict__ b3, float* __restrict__ outg, int N) {
  SmemT* S = (SmemT*)smem_dyn;
  const int row0 = blockIdx.x * 128;
  const float4* f4 = (const float4*)feat;
  for (int i = threadIdx.x; i < 128 * 32; i += 512) {
    int r = i >> 5, kq = i & 31;
    int row = row0 + r;
    float4 v = make_float4(0.f, 0.f, 0.f, 0.f);
    if (row < N) v = __ldg(&f4[(size_t)row * 32 + kq]);
    ((float4*)S->xs)[r * 32 + kq] = v;
  }
  load_weights(w1, b1, HHD, HD, S->ws, S->bias);
  __syncthreads();
  gemm_stage<HD, HHD, true, 0>(S->xs, S->ws, S->bias, S->as1, nullptr, nullptr,
                               nullptr, row0, N);
  __syncthreads();
  load_weights(w2, b2, HHD, HHD, S->ws, S->bias);
  __syncthreads();
  gemm_stage<HHD, HHD, true, 0>(S->as1, S->ws, S->bias, S->as2, nullptr,
                                nullptr, nullptr, row0, N);
  __syncthreads();
  load_weights(w3, b3, HD, HHD, S->ws, S->bias);
  __syncthreads();
  gemm_stage<HHD, HD, false, 1>(S->as2, S->ws, S->bias, nullptr, outg, nullptr,
                                nullptr, row0, N);
}

// ---------------- kernel B: edge gather + scatter-add ----------------
__global__ __launch_bounds__(256) void scatter_kernel(
    const float* __restrict__ feat, const float* __restrict__ invf,
    const int* __restrict__ src, const int* __restrict__ dst,
    const int* __restrict__ r, float* __restrict__ nsum,
    float* __restrict__ deg, int E) {
  const int e = blockIdx.x * 8 + (threadIdx.x >> 5);
  if (e >= E) return;
  const int lane = threadIdx.x & 31;
  const int s = __ldg(src + e);
  const int d = __ldg(dst + e);
  const int rr = __ldg(r + e);
  const float* base = rr ? invf : feat;
  const float4 v = __ldg((const float4*)(base + (size_t)s * HD) + lane);
  float* o = nsum + (size_t)d * HD + lane * 4;
  atomicAdd(o + 0, v.x);
  atomicAdd(o + 1, v.y);
  atomicAdd(o + 2, v.z);
  atomicAdd(o + 3, v.w);
  if (lane == 0) atomicAdd(deg + d, 1.0f);
}

// --------- kernel C: node apply: mean -> and-MLP -> inv-MLP -> select ---------
__global__ __launch_bounds__(512, 1) void node_kernel(
    const float* __restrict__ nsum, const float* __restrict__ deg,
    const float* __restrict__ aw1, const float* __restrict__ ab1,
    const float* __restrict__ aw2, const float* __restrict__ ab2,
    const float* __restrict__ aw3, const float* __restrict__ ab3,
    const float* __restrict__ iw1, const float* __restrict__ ib1,
    const float* __restrict__ iw2, const float* __restrict__ ib2,
    const float* __restrict__ iw3, const float* __restrict__ ib3,
    const int* __restrict__ inv, float* __restrict__ outg, int N) {
  SmemT* S = (SmemT*)smem_dyn;
  const int row0 = blockIdx.x * 128;
  const float4* n4 = (const float4*)nsum;
  for (int i = threadIdx.x; i < 128 * 32; i += 512) {
    int r = i >> 5, kq = i & 31;
    int row = row0 + r;
    float4 v = make_float4(0.f, 0.f, 0.f, 0.f);
    if (row < N) {
      float invd = 1.0f / fmaxf(__ldg(deg + row), 1.0f);
      v = __ldg(&n4[(size_t)row * 32 + kq]);
      v.x *= invd; v.y *= invd; v.z *= invd; v.w *= invd;
    }
    ((float4*)S->xs)[r * 32 + kq] = v;
  }
  // and-MLP
  load_weights(aw1, ab1, HHD, HD, S->ws, S->bias);
  __syncthreads();
  gemm_stage<HD, HHD, true, 0>(S->xs, S->ws, S->bias, S->as1, nullptr, nullptr,
                               nullptr, row0, N);
  __syncthreads();
  load_weights(aw2, ab2, HHD, HHD, S->ws, S->bias);
  __syncthreads();
  gemm_stage<HHD, HHD, true, 0>(S->as1, S->ws, S->bias, S->as2, nullptr,
                                nullptr, nullptr, row0, N);
  __syncthreads();
  load_weights(aw3, ab3, HD, HHD, S->ws, S->bias);
  __syncthreads();
  // res -> xs (stride 128), no activation
  gemm_stage<HHD, HD, false, 0>(S->as2, S->ws, S->bias, S->xs, nullptr,
                                nullptr, nullptr, row0, N);
  __syncthreads();
  // inv-MLP on res
  load_weights(iw1, ib1, HHD, HD, S->ws, S->bias);
  __syncthreads();
  gemm_stage<HD, HHD, true, 0>(S->xs, S->ws, S->bias, S->as1, nullptr, nullptr,
                               nullptr, row0, N);
  __syncthreads();
  load_weights(iw2, ib2, HHD, HHD, S->ws, S->bias);
  __syncthreads();
  gemm_stage<HHD, HHD, true, 0>(S->as1, S->ws, S->bias, S->as2, nullptr,
                                nullptr, nullptr, row0, N);
  __syncthreads();
  load_weights(iw3, ib3, HD, HHD, S->ws, S->bias);
  __syncthreads();
  // final: out = inv ? mlp_inv(res) : res
  gemm_stage<HHD, HD, false, 2>(S->as2, S->ws, S->bias, nullptr, outg, S->xs,
                                inv, row0, N);
}

// ---------------- launch ----------------
extern "C" void kernel_launch(void* const* d_in, const int* in_sizes, int n_in,
                              void* d_out, int out_size) {
  const float* feat = (const float*)d_in[0];
  const int* src = (const int*)d_in[1];
  const int* dst = (const int*)d_in[2];
  const int* r = (const int*)d_in[3];
  const int* inv = (const int*)d_in[4];
  const float* iw1 = (const float*)d_in[5];
  const float* ib1 = (const float*)d_in[6];
  const float* iw2 = (const float*)d_in[7];
  const float* ib2 = (const float*)d_in[8];
  const float* iw3 = (const float*)d_in[9];
  const float* ib3 = (const float*)d_in[10];
  const float* aw1 = (const float*)d_in[11];
  const float* ab1 = (const float*)d_in[12];
  const float* aw2 = (const float*)d_in[13];
  const float* ab2 = (const float*)d_in[14];
  const float* aw3 = (const float*)d_in[15];
  const float* ab3 = (const float*)d_in[16];
  float* out = (float*)d_out;

  const int N = in_sizes[0] / HD;
  const int E = in_sizes[1];

  float *p_invf, *p_nsum, *p_deg;
  cudaGetSymbolAddress((void**)&p_invf, g_inv_feat);
  cudaGetSymbolAddress((void**)&p_nsum, g_nsum);
  cudaGetSymbolAddress((void**)&p_deg, g_deg);

  const int smem = (int)sizeof(SmemT);
  cudaFuncSetAttribute(mlp_inv_kernel,
                       cudaFuncAttributeMaxDynamicSharedMemorySize, smem);
  cudaFuncSetAttribute(node_kernel,
                       cudaFuncAttributeMaxDynamicSharedMemorySize, smem);

  cudaMemsetAsync(p_nsum, 0, (size_t)N * HD * sizeof(float));
  cudaMemsetAsync(p_deg, 0, (size_t)N * sizeof(float));

  const int nblocks = (N + 127) / 128;
  mlp_inv_kernel<<<nblocks, 512, smem>>>(feat, iw1, ib1, iw2, ib2, iw3, ib3,
                                         p_invf, N);
  scatter_kernel<<<(E + 7) / 8, 256>>>(feat, p_invf, src, dst, r, p_nsum,
                                       p_deg, E);
  node_kernel<<<nblocks, 512, smem>>>(p_nsum, p_deg, aw1, ab1, aw2, ab2, aw3,
                                      ab3, iw1, ib1, iw2, ib2, iw3, ib3, inv,
                                      out, N);
}

// round 5
// speedup vs baseline: 1.1484x; 1.0670x over previous
#include <cuda_runtime.h>
#include <cstdint>

#define HD 128
#define HHD 64
#define NMAX 100000

// ---------------- device scratch (no allocations allowed) ----------------
__device__ float g_inv_feat[NMAX * HD];   // mlp_inv(feat) for every node
__device__ float g_nsum[NMAX * HD];       // segment sum of messages
__device__ float g_deg[NMAX];             // in-degree (float)

// ---------------- shared memory layout for MLP kernels ----------------
// Padded strides: K+4 floats per row -> fragment loads are bank-conflict-free
// (bank = (4*row + col) % 32 covers all 32 banks for an 8x4 lane footprint).
struct SmemM {
  float xs[128 * 132];   // input tile / res tile, stride 132   67584 B
  float ws[8704];        // one weight layer, stride K+4        34816 B max
  float as1[128 * 68];   // activation buffer, stride 68        34816 B
  float as2[128 * 68];   // activation buffer, stride 68        34816 B
  float bias[128];
};

extern __shared__ float smem_dyn[];

// ---------------- tf32 helpers ----------------
__device__ __forceinline__ uint32_t f2tf(float x) {
  uint32_t r;
  asm("cvt.rna.tf32.f32 %0, %1;" : "=r"(r) : "f"(x));
  return r;
}
__device__ __forceinline__ void split3(float x, uint32_t& hi, uint32_t& lo) {
  hi = f2tf(x);
  lo = f2tf(x - __uint_as_float(hi));
}
__device__ __forceinline__ void mma_tf32(float* c, const uint32_t* a,
                                         const uint32_t* b) {
  asm volatile(
      "mma.sync.aligned.m16n8k8.row.col.f32.tf32.tf32.f32 "
      "{%0,%1,%2,%3}, {%4,%5,%6,%7}, {%8,%9}, {%0,%1,%2,%3};"
      : "+f"(c[0]), "+f"(c[1]), "+f"(c[2]), "+f"(c[3])
      : "r"(a[0]), "r"(a[1]), "r"(a[2]), "r"(a[3]), "r"(b[0]), "r"(b[1]));
}

// Stage one weight layer [C][K] row-major into smem with stride K+4 (row
// starts stay 16B-aligned since (K+4)*4 is a multiple of 16). Plus bias.
template <int K, int C>
__device__ __forceinline__ void load_weights(const float* __restrict__ wg,
                                             const float* __restrict__ bg,
                                             float* ws, float* bias) {
  constexpr int SLOTS = K / 4;
  const float4* wg4 = (const float4*)wg;
  for (int i = threadIdx.x; i < C * SLOTS; i += 512) {
    int c = i / SLOTS;
    int s = i - c * SLOTS;
    ((float4*)(ws + c * (K + 4)))[s] = __ldg(&wg4[i]);
  }
  if ((int)threadIdx.x < C) bias[threadIdx.x] = __ldg(bg + threadIdx.x);
}

// One 3xTF32 GEMM stage: out[r][c] = act( in[r][:] . w[c][:] + bias[c] )
// 128 rows, 512 threads = 16 warps. Warp w: rows (w%8)*16..+15, cols
// (w/8)*(C/2)..+(C/2)-1 as C/16 m16n8 tiles. K consumed in k=8 steps.
// OUTMODE: 0 = write smem out_s (stride C+4)
//          1 = write global out_g rows (stride HD), guarded by N
//          2 = global write with per-row select: inv ? acc : res_s (stride 132)
template <int K, int C, bool RELU, int OUTMODE>
__device__ __forceinline__ void gemm_stage(
    const float* __restrict__ in_s, const float* __restrict__ ws,
    const float* __restrict__ bias, float* __restrict__ out_s,
    float* __restrict__ out_g, const float* __restrict__ res_s,
    const int* __restrict__ invflag, int row0, int N) {
  constexpr int SI = K + 4;
  constexpr int SO = C + 4;
  constexpr int NT = C / 16;   // n-tiles per warp
  constexpr int KS = K / 8;    // k-steps
  const int lane = threadIdx.x & 31;
  const int warp = threadIdx.x >> 5;
  const int wm = warp & 7;     // row group (16 rows)
  const int wn = warp >> 3;    // column half
  const int gid = lane >> 2;   // 0..7
  const int tid4 = lane & 3;   // 0..3
  const int r0 = wm * 16 + gid;
  const int r1 = r0 + 8;
  const int ncol0 = wn * (C / 2);

  float c[NT][4];
#pragma unroll
  for (int j = 0; j < NT; ++j)
#pragma unroll
    for (int q = 0; q < 4; ++q) c[j][q] = 0.f;

#pragma unroll 4
  for (int ks = 0; ks < KS; ++ks) {
    const int k0 = ks * 8;
    float af[4];
    af[0] = in_s[r0 * SI + k0 + tid4];
    af[1] = in_s[r1 * SI + k0 + tid4];
    af[2] = in_s[r0 * SI + k0 + tid4 + 4];
    af[3] = in_s[r1 * SI + k0 + tid4 + 4];
    uint32_t ah[4], al[4];
#pragma unroll
    for (int t = 0; t < 4; ++t) split3(af[t], ah[t], al[t]);
#pragma unroll
    for (int j = 0; j < NT; ++j) {
      const float* wrow = ws + (ncol0 + j * 8 + gid) * SI + k0 + tid4;
      float bf0 = wrow[0];
      float bf1 = wrow[4];
      uint32_t bh[2], bl[2];
      split3(bf0, bh[0], bl[0]);
      split3(bf1, bh[1], bl[1]);
      mma_tf32(c[j], al, bh);   // low-order terms first
      mma_tf32(c[j], ah, bl);
      mma_tf32(c[j], ah, bh);
    }
  }

#pragma unroll
  for (int j = 0; j < NT; ++j) {
    const int col = ncol0 + j * 8 + 2 * tid4;
    const float bx = bias[col];
    const float by = bias[col + 1];
    float v0 = c[j][0] + bx, v1 = c[j][1] + by;
    float v2 = c[j][2] + bx, v3 = c[j][3] + by;
    if (RELU) {
      v0 = v0 >= 0.f ? v0 : 0.01f * v0;
      v1 = v1 >= 0.f ? v1 : 0.01f * v1;
      v2 = v2 >= 0.f ? v2 : 0.01f * v2;
      v3 = v3 >= 0.f ? v3 : 0.01f * v3;
    }
    if (OUTMODE == 0) {
      *(float2*)(out_s + r0 * SO + col) = make_float2(v0, v1);
      *(float2*)(out_s + r1 * SO + col) = make_float2(v2, v3);
    } else {
      const int grow0 = row0 + r0;
      const int grow1 = row0 + r1;
      if (grow0 < N) {
        float2 o = make_float2(v0, v1);
        if (OUTMODE == 2 && __ldg(invflag + grow0) == 0)
          o = *(const float2*)(res_s + r0 * 132 + col);
        *(float2*)(out_g + (size_t)grow0 * HD + col) = o;
      }
      if (grow1 < N) {
        float2 o = make_float2(v2, v3);
        if (OUTMODE == 2 && __ldg(invflag + grow1) == 0)
          o = *(const float2*)(res_s + r1 * 132 + col);
        *(float2*)(out_g + (size_t)grow1 * HD + col) = o;
      }
    }
  }
}

// ---------------- kernel A: inv_feat = mlp3_inv(feat) ----------------
__global__ __launch_bounds__(512, 1) void mlp_inv_kernel(
    const float* __restrict__ feat, const float* __restrict__ w1,
    const float* __restrict__ b1, const float* __restrict__ w2,
    const float* __restrict__ b2, const float* __restrict__ w3,
    const float* __restrict__ b3, float* __restrict__ outg, int N) {
  SmemM* S = (SmemM*)smem_dyn;
  const int row0 = blockIdx.x * 128;
  const float4* f4 = (const float4*)feat;
  for (int i = threadIdx.x; i < 128 * 32; i += 512) {
    int r = i >> 5, kq = i & 31;
    int row = row0 + r;
    float4 v = make_float4(0.f, 0.f, 0.f, 0.f);
    if (row < N) v = __ldg(&f4[(size_t)row * 32 + kq]);
    ((float4*)(S->xs + r * 132))[kq] = v;
  }
  load_weights<HD, HHD>(w1, b1, S->ws, S->bias);
  __syncthreads();
  gemm_stage<HD, HHD, true, 0>(S->xs, S->ws, S->bias, S->as1, nullptr, nullptr,
                               nullptr, row0, N);
  __syncthreads();
  load_weights<HHD, HHD>(w2, b2, S->ws, S->bias);
  __syncthreads();
  gemm_stage<HHD, HHD, true, 0>(S->as1, S->ws, S->bias, S->as2, nullptr,
                                nullptr, nullptr, row0, N);
  __syncthreads();
  load_weights<HHD, HD>(w3, b3, S->ws, S->bias);
  __syncthreads();
  gemm_stage<HHD, HD, false, 1>(S->as2, S->ws, S->bias, nullptr, outg, nullptr,
                                nullptr, row0, N);
}

// ---------------- kernel B: edge gather + scatter-add ----------------
__global__ __launch_bounds__(256) void scatter_kernel(
    const float* __restrict__ feat, const float* __restrict__ invf,
    const int* __restrict__ src, const int* __restrict__ dst,
    const int* __restrict__ r, float* __restrict__ nsum,
    float* __restrict__ deg, int E) {
  const int e = blockIdx.x * 8 + (threadIdx.x >> 5);
  if (e >= E) return;
  const int lane = threadIdx.x & 31;
  const int s = __ldg(src + e);
  const int d = __ldg(dst + e);
  const int rr = __ldg(r + e);
  const float* base = rr ? invf : feat;
  const float4 v = __ldg((const float4*)(base + (size_t)s * HD) + lane);
  float* o = nsum + (size_t)d * HD + lane * 4;
  atomicAdd(o + 0, v.x);
  atomicAdd(o + 1, v.y);
  atomicAdd(o + 2, v.z);
  atomicAdd(o + 3, v.w);
  if (lane == 0) atomicAdd(deg + d, 1.0f);
}

// --------- kernel C: node apply: mean -> and-MLP -> inv-MLP -> select ---------
__global__ __launch_bounds__(512, 1) void node_kernel(
    const float* __restrict__ nsum, const float* __restrict__ deg,
    const float* __restrict__ aw1, const float* __restrict__ ab1,
    const float* __restrict__ aw2, const float* __restrict__ ab2,
    const float* __restrict__ aw3, const float* __restrict__ ab3,
    const float* __restrict__ iw1, const float* __restrict__ ib1,
    const float* __restrict__ iw2, const float* __restrict__ ib2,
    const float* __restrict__ iw3, const float* __restrict__ ib3,
    const int* __restrict__ inv, float* __restrict__ outg, int N) {
  SmemM* S = (SmemM*)smem_dyn;
  const int row0 = blockIdx.x * 128;
  const float4* n4 = (const float4*)nsum;
  for (int i = threadIdx.x; i < 128 * 32; i += 512) {
    int r = i >> 5, kq = i & 31;
    int row = row0 + r;
    float4 v = make_float4(0.f, 0.f, 0.f, 0.f);
    if (row < N) {
      float invd = 1.0f / fmaxf(__ldg(deg + row), 1.0f);
      v = __ldg(&n4[(size_t)row * 32 + kq]);
      v.x *= invd; v.y *= invd; v.z *= invd; v.w *= invd;
    }
    ((float4*)(S->xs + r * 132))[kq] = v;
  }
  // and-MLP
  load_weights<HD, HHD>(aw1, ab1, S->ws, S->bias);
  __syncthreads();
  gemm_stage<HD, HHD, true, 0>(S->xs, S->ws, S->bias, S->as1, nullptr, nullptr,
                               nullptr, row0, N);
  __syncthreads();
  load_weights<HHD, HHD>(aw2, ab2, S->ws, S->bias);
  __syncthreads();
  gemm_stage<HHD, HHD, true, 0>(S->as1, S->ws, S->bias, S->as2, nullptr,
                                nullptr, nullptr, row0, N);
  __syncthreads();
  load_weights<HHD, HD>(aw3, ab3, S->ws, S->bias);
  __syncthreads();
  // res -> xs (stride 132), no activation
  gemm_stage<HHD, HD, false, 0>(S->as2, S->ws, S->bias, S->xs, nullptr,
                                nullptr, nullptr, row0, N);
  __syncthreads();
  // inv-MLP on res
  load_weights<HD, HHD>(iw1, ib1, S->ws, S->bias);
  __syncthreads();
  gemm_stage<HD, HHD, true, 0>(S->xs, S->ws, S->bias, S->as1, nullptr, nullptr,
                               nullptr, row0, N);
  __syncthreads();
  load_weights<HHD, HHD>(iw2, ib2, S->ws, S->bias);
  __syncthreads();
  gemm_stage<HHD, HHD, true, 0>(S->as1, S->ws, S->bias, S->as2, nullptr,
                                nullptr, nullptr, row0, N);
  __syncthreads();
  load_weights<HHD, HD>(iw3, ib3, S->ws, S->bias);
  __syncthreads();
  // final: out = inv ? mlp_inv(res) : res   (res lives in xs, stride 132)
  gemm_stage<HHD, HD, false, 2>(S->as2, S->ws, S->bias, nullptr, outg, S->xs,
                                inv, row0, N);
}

// ---------------- launch ----------------
extern "C" void kernel_launch(void* const* d_in, const int* in_sizes, int n_in,
                              void* d_out, int out_size) {
  const float* feat = (const float*)d_in[0];
  const int* src = (const int*)d_in[1];
  const int* dst = (const int*)d_in[2];
  const int* r = (const int*)d_in[3];
  const int* inv = (const int*)d_in[4];
  const float* iw1 = (const float*)d_in[5];
  const float* ib1 = (const float*)d_in[6];
  const float* iw2 = (const float*)d_in[7];
  const float* ib2 = (const float*)d_in[8];
  const float* iw3 = (const float*)d_in[9];
  const float* ib3 = (const float*)d_in[10];
  const float* aw1 = (const float*)d_in[11];
  const float* ab1 = (const float*)d_in[12];
  const float* aw2 = (const float*)d_in[13];
  const float* ab2 = (const float*)d_in[14];
  const float* aw3 = (const float*)d_in[15];
  const float* ab3 = (const float*)d_in[16];
  float* out = (float*)d_out;

  const int N = in_sizes[0] / HD;
  const int E = in_sizes[1];

  float *p_invf, *p_nsum, *p_deg;
  cudaGetSymbolAddress((void**)&p_invf, g_inv_feat);
  cudaGetSymbolAddress((void**)&p_nsum, g_nsum);
  cudaGetSymbolAddress((void**)&p_deg, g_deg);

  const int smem = (int)sizeof(SmemM);
  cudaFuncSetAttribute(mlp_inv_kernel,
                       cudaFuncAttributeMaxDynamicSharedMemorySize, smem);
  cudaFuncSetAttribute(node_kernel,
                       cudaFuncAttributeMaxDynamicSharedMemorySize, smem);

  cudaMemsetAsync(p_nsum, 0, (size_t)N * HD * sizeof(float));
  cudaMemsetAsync(p_deg, 0, (size_t)N * sizeof(float));

  const int nblocks = (N + 127) / 128;
  mlp_inv_kernel<<<nblocks, 512, smem>>>(feat, iw1, ib1, iw2, ib2, iw3, ib3,
                                         p_invf, N);
  scatter_kernel<<<(E + 7) / 8, 256>>>(feat, p_invf, src, dst, r, p_nsum,
                                       p_deg, E);
  node_kernel<<<nblocks, 512, smem>>>(p_nsum, p_deg, aw1, ab1, aw2, ab2, aw3,
                                      ab3, iw1, ib1, iw2, ib2, iw3, ib3, inv,
                                      out, N);
}